// round 15
// baseline (speedup 1.0000x reference)
#include <cuda_runtime.h>
#include <cstdint>

#define Bn   4096
#define Tn   64
#define DIN  300
#define Hn   3
#define DIN4 75      // 300/4
#define C2LE 2.885390081777927f   // 2*log2(e): folded into xb and W_hh

// lengths may arrive as int32 or int64. Values in [1,64] so for int64 the
// high word of element 0 — ((int*)L)[1] — is 0; for int32 it is lengths[1]>=1.
__device__ __forceinline__ int detect_is64(const void* L) {
    return ((const int*)L)[1] == 0;
}
__device__ __forceinline__ int length_at(const void* L, int b, int is64) {
    if (is64) return (int)((const long long*)L)[b];
    return ((const int*)L)[b];
}

// tanh from pre-scaled argument a = 2*log2(e)*x:
//   tanh(x) = 1 - 2/(2^a + 1).  MUFU EX2 + MUFU RCP, few-ulp, saturates right.
__device__ __forceinline__ float tanh_pre(float a) {
    float e, r;
    asm("ex2.approx.f32 %0, %1;" : "=f"(e) : "f"(a));
    asm("rcp.approx.f32 %0, %1;" : "=f"(r) : "f"(e + 1.0f));
    return fmaf(-2.0f, r, 1.0f);
}

// ---------------------------------------------------------------------------
// Fused kernel: one block (128 threads) per sample.
//  Phase A: 4 warps project rows t = warp, warp+4, ... (< len) straight into
//           shared memory (pre-scaled by 2log2e). Dead rows never loaded.
//  Phase B: thread 0 runs the 3-wide recurrence out of smem; serial tails of
//           different blocks overlap across the SM, DRAM stays saturated.
// xb never touches DRAM; the old k_rnn kernel (9us) disappears entirely.
// ---------------------------------------------------------------------------
__global__ __launch_bounds__(128) void k_fused(
    const float* __restrict__ x,
    const void*  __restrict__ L,
    const float* __restrict__ W_ih,
    const float* __restrict__ W_hh,
    const float* __restrict__ b_ih,
    const float* __restrict__ b_hh,
    float*       __restrict__ out)
{
    __shared__ float4 sxb[Tn];          // 1 KB: pre-scaled xb for this sample

    const int b    = blockIdx.x;
    const int warp = threadIdx.x >> 5;
    const int lane = threadIdx.x & 31;

    const int is64 = detect_is64(L);
    const int len  = length_at(L, b, is64);   // in [1, 64]

    // ---- per-lane register weight slices: w[h][k] covers cols 4*(lane+32k) ----
    const float4* __restrict__ W4 = (const float4*)W_ih;
    float4 w[Hn][3];
    #pragma unroll
    for (int h = 0; h < Hn; ++h)
        #pragma unroll
        for (int k = 0; k < 3; ++k) {
            const int j = lane + 32 * k;
            w[h][k] = (j < DIN4) ? W4[h * DIN4 + j] : make_float4(0.f,0.f,0.f,0.f);
        }

    const float bs0 = (b_ih[0] + b_hh[0]) * C2LE;
    const float bs1 = (b_ih[1] + b_hh[1]) * C2LE;
    const float bs2 = (b_ih[2] + b_hh[2]) * C2LE;

    // ---- Phase A: project live rows of this sample into smem ----
    const float4* __restrict__ xbase = (const float4*)x + (size_t)b * Tn * DIN4;
    const bool p2 = (lane < DIN4 - 64);           // lanes 0..10 carry wave 2

    for (int t = warp; t < len; t += 4) {
        const float4* __restrict__ xr = xbase + (size_t)t * DIN4;
        // 3 load waves issued back-to-back (2-3 LDG.128 in flight per warp;
        // aggregate MLP across ~28 warps/SM saturates DRAM)
        const float4 v0 = xr[lane];
        const float4 v1 = xr[lane + 32];
        const float4 v2 = p2 ? xr[lane + 64] : make_float4(0.f,0.f,0.f,0.f);

        float a0, a1, a2;
        {
            float s0, s1, s2;
            s0 = v0.x*w[0][0].x + v0.y*w[0][0].y + v0.z*w[0][0].z + v0.w*w[0][0].w;
            s1 = v0.x*w[1][0].x + v0.y*w[1][0].y + v0.z*w[1][0].z + v0.w*w[1][0].w;
            s2 = v0.x*w[2][0].x + v0.y*w[2][0].y + v0.z*w[2][0].z + v0.w*w[2][0].w;
            s0 += v1.x*w[0][1].x + v1.y*w[0][1].y + v1.z*w[0][1].z + v1.w*w[0][1].w;
            s1 += v1.x*w[1][1].x + v1.y*w[1][1].y + v1.z*w[1][1].z + v1.w*w[1][1].w;
            s2 += v1.x*w[2][1].x + v1.y*w[2][1].y + v1.z*w[2][1].z + v1.w*w[2][1].w;
            s0 += v2.x*w[0][2].x + v2.y*w[0][2].y + v2.z*w[0][2].z + v2.w*w[0][2].w;
            s1 += v2.x*w[1][2].x + v2.y*w[1][2].y + v2.z*w[1][2].z + v2.w*w[1][2].w;
            s2 += v2.x*w[2][2].x + v2.y*w[2][2].y + v2.z*w[2][2].z + v2.w*w[2][2].w;
            a0 = s0; a1 = s1; a2 = s2;
        }
        #pragma unroll
        for (int off = 16; off; off >>= 1) {
            a0 += __shfl_xor_sync(0xffffffffu, a0, off);
            a1 += __shfl_xor_sync(0xffffffffu, a1, off);
            a2 += __shfl_xor_sync(0xffffffffu, a2, off);
        }
        if (lane == 0) {
            float4 o;
            o.x = fmaf(a0, C2LE, bs0);
            o.y = fmaf(a1, C2LE, bs1);
            o.z = fmaf(a2, C2LE, bs2);
            o.w = 0.f;
            sxb[t] = o;
        }
    }

    __syncthreads();

    // ---- Phase B: single-thread recurrence out of smem ----
    if (threadIdx.x == 0) {
        const float w00 = W_hh[0]*C2LE, w01 = W_hh[1]*C2LE, w02 = W_hh[2]*C2LE;
        const float w10 = W_hh[3]*C2LE, w11 = W_hh[4]*C2LE, w12 = W_hh[5]*C2LE;
        const float w20 = W_hh[6]*C2LE, w21 = W_hh[7]*C2LE, w22 = W_hh[8]*C2LE;

        const int lm1 = len - 1;
        float4 cur = sxb[0];
        float4 nxt = sxb[1 < lm1 ? 1 : lm1];

        float h0 = 0.f, h1 = 0.f, h2 = 0.f;

        #pragma unroll 4
        for (int t = 0; t < len; ++t) {
            const float x0 = cur.x, x1 = cur.y, x2 = cur.z;
            cur = nxt;
            const int tp = (t + 2 < lm1) ? (t + 2) : lm1;
            nxt = sxb[tp];

            const float a0 = x0 + h0*w00 + h1*w01 + h2*w02;
            const float a1 = x1 + h0*w10 + h1*w11 + h2*w12;
            const float a2 = x2 + h0*w20 + h1*w21 + h2*w22;
            h0 = tanh_pre(a0);
            h1 = tanh_pre(a1);
            h2 = tanh_pre(a2);
        }

        out[b * Hn + 0] = h0;
        out[b * Hn + 1] = h1;
        out[b * Hn + 2] = h2;
    }
}

extern "C" void kernel_launch(void* const* d_in, const int* in_sizes, int n_in,
                              void* d_out, int out_size)
{
    const float* x    = (const float*)d_in[0];
    const void*  L    = d_in[1];
    const float* W_ih = (const float*)d_in[2];
    const float* W_hh = (const float*)d_in[3];
    const float* b_ih = (const float*)d_in[4];
    const float* b_hh = (const float*)d_in[5];
    float* out = (float*)d_out;

    // one block per sample; single kernel -> ncu capture always lands here
    k_fused<<<Bn, 128>>>(x, L, W_ih, W_hh, b_ih, b_hh, out);
}

// round 16
// speedup vs baseline: 1.2509x; 1.2509x over previous
#include <cuda_runtime.h>
#include <cstdint>

#define Bn   4096
#define Tn   64
#define DIN  300
#define Hn   3
#define DIN4 75      // 300/4
#define C2LE 2.885390081777927f   // 2*log2(e): folded into xb and W_hh

// lengths may arrive as int32 or int64. Values in [1,64] so for int64 the
// high word of element 0 — ((int*)L)[1] — is 0; for int32 it is lengths[1]>=1.
__device__ __forceinline__ int detect_is64(const void* L) {
    return ((const int*)L)[1] == 0;
}
__device__ __forceinline__ int length_at(const void* L, int b, int is64) {
    if (is64) return (int)((const long long*)L)[b];
    return ((const int*)L)[b];
}

// tanh from pre-scaled argument a = 2*log2(e)*x:
//   tanh(x) = 1 - 2/(2^a + 1).  MUFU EX2 + MUFU RCP, few-ulp, saturates right.
__device__ __forceinline__ float tanh_pre(float a) {
    float e, r;
    asm("ex2.approx.f32 %0, %1;" : "=f"(e) : "f"(a));
    asm("rcp.approx.f32 %0, %1;" : "=f"(r) : "f"(e + 1.0f));
    return fmaf(-2.0f, r, 1.0f);
}

// ---------------------------------------------------------------------------
// Fused kernel: one block (128 threads) per sample.
//  Phase A: 4 warps project rows t = warp, warp+4, ... (< len) straight into
//           shared memory, with the NEXT row's 3 loads issued before the
//           current row's FMA/reduce (1-ahead software pipeline -> MLP ~6/warp,
//           DRAM latency hidden behind compute).
//  Phase B: thread 0 runs the 3-wide recurrence out of smem; serial tails of
//           different blocks overlap across the SM.
// ---------------------------------------------------------------------------
__global__ __launch_bounds__(128) void k_fused(
    const float* __restrict__ x,
    const void*  __restrict__ L,
    const float* __restrict__ W_ih,
    const float* __restrict__ W_hh,
    const float* __restrict__ b_ih,
    const float* __restrict__ b_hh,
    float*       __restrict__ out)
{
    __shared__ float4 sxb[Tn];          // 1 KB: pre-scaled xb for this sample

    const int b    = blockIdx.x;
    const int warp = threadIdx.x >> 5;
    const int lane = threadIdx.x & 31;

    const int is64 = detect_is64(L);
    const int len  = length_at(L, b, is64);   // in [1, 64]

    // ---- per-lane register weight slices: w[h][k] covers cols 4*(lane+32k) ----
    const float4* __restrict__ W4 = (const float4*)W_ih;
    float4 w[Hn][3];
    #pragma unroll
    for (int h = 0; h < Hn; ++h)
        #pragma unroll
        for (int k = 0; k < 3; ++k) {
            const int j = lane + 32 * k;
            w[h][k] = (j < DIN4) ? W4[h * DIN4 + j] : make_float4(0.f,0.f,0.f,0.f);
        }

    const float bs0 = (b_ih[0] + b_hh[0]) * C2LE;
    const float bs1 = (b_ih[1] + b_hh[1]) * C2LE;
    const float bs2 = (b_ih[2] + b_hh[2]) * C2LE;

    // ---- Phase A: pipelined projection of live rows into smem ----
    const float4* __restrict__ xbase = (const float4*)x + (size_t)b * Tn * DIN4;
    const bool p2 = (lane < DIN4 - 64);           // lanes 0..10 carry wave 2

    int t = warp;
    if (t < len) {
        // prologue: loads for first row
        const float4* __restrict__ xr = xbase + (size_t)t * DIN4;
        float4 v0 = xr[lane];
        float4 v1 = xr[lane + 32];
        float4 v2 = p2 ? xr[lane + 64] : make_float4(0.f,0.f,0.f,0.f);

        for (; t < len; t += 4) {
            // issue NEXT row's loads before touching current row's values
            const int tn = (t + 4 < len) ? (t + 4) : t;   // clamp: redundant L1 hit
            const float4* __restrict__ xn = xbase + (size_t)tn * DIN4;
            float4 u0 = xn[lane];
            float4 u1 = xn[lane + 32];
            float4 u2 = p2 ? xn[lane + 64] : make_float4(0.f,0.f,0.f,0.f);

            float a0, a1, a2;
            {
                float s0, s1, s2;
                s0 = v0.x*w[0][0].x + v0.y*w[0][0].y + v0.z*w[0][0].z + v0.w*w[0][0].w;
                s1 = v0.x*w[1][0].x + v0.y*w[1][0].y + v0.z*w[1][0].z + v0.w*w[1][0].w;
                s2 = v0.x*w[2][0].x + v0.y*w[2][0].y + v0.z*w[2][0].z + v0.w*w[2][0].w;
                s0 += v1.x*w[0][1].x + v1.y*w[0][1].y + v1.z*w[0][1].z + v1.w*w[0][1].w;
                s1 += v1.x*w[1][1].x + v1.y*w[1][1].y + v1.z*w[1][1].z + v1.w*w[1][1].w;
                s2 += v1.x*w[2][1].x + v1.y*w[2][1].y + v1.z*w[2][1].z + v1.w*w[2][1].w;
                s0 += v2.x*w[0][2].x + v2.y*w[0][2].y + v2.z*w[0][2].z + v2.w*w[0][2].w;
                s1 += v2.x*w[1][2].x + v2.y*w[1][2].y + v2.z*w[1][2].z + v2.w*w[1][2].w;
                s2 += v2.x*w[2][2].x + v2.y*w[2][2].y + v2.z*w[2][2].z + v2.w*w[2][2].w;
                a0 = s0; a1 = s1; a2 = s2;
            }
            #pragma unroll
            for (int off = 16; off; off >>= 1) {
                a0 += __shfl_xor_sync(0xffffffffu, a0, off);
                a1 += __shfl_xor_sync(0xffffffffu, a1, off);
                a2 += __shfl_xor_sync(0xffffffffu, a2, off);
            }
            if (lane == 0) {
                float4 o;
                o.x = fmaf(a0, C2LE, bs0);
                o.y = fmaf(a1, C2LE, bs1);
                o.z = fmaf(a2, C2LE, bs2);
                o.w = 0.f;
                sxb[t] = o;
            }

            v0 = u0; v1 = u1; v2 = u2;    // rotate pipeline
        }
    }

    __syncthreads();

    // ---- Phase B: single-thread recurrence out of smem ----
    if (threadIdx.x == 0) {
        const float w00 = W_hh[0]*C2LE, w01 = W_hh[1]*C2LE, w02 = W_hh[2]*C2LE;
        const float w10 = W_hh[3]*C2LE, w11 = W_hh[4]*C2LE, w12 = W_hh[5]*C2LE;
        const float w20 = W_hh[6]*C2LE, w21 = W_hh[7]*C2LE, w22 = W_hh[8]*C2LE;

        const int lm1 = len - 1;
        float4 cur = sxb[0];
        float4 nxt = sxb[1 < lm1 ? 1 : lm1];

        float h0 = 0.f, h1 = 0.f, h2 = 0.f;

        #pragma unroll 4
        for (int tt = 0; tt < len; ++tt) {
            const float x0 = cur.x, x1 = cur.y, x2 = cur.z;
            cur = nxt;
            const int tp = (tt + 2 < lm1) ? (tt + 2) : lm1;
            nxt = sxb[tp];

            const float a0 = x0 + h0*w00 + h1*w01 + h2*w02;
            const float a1 = x1 + h0*w10 + h1*w11 + h2*w12;
            const float a2 = x2 + h0*w20 + h1*w21 + h2*w22;
            h0 = tanh_pre(a0);
            h1 = tanh_pre(a1);
            h2 = tanh_pre(a2);
        }

        out[b * Hn + 0] = h0;
        out[b * Hn + 1] = h1;
        out[b * Hn + 2] = h2;
    }
}

extern "C" void kernel_launch(void* const* d_in, const int* in_sizes, int n_in,
                              void* d_out, int out_size)
{
    const float* x    = (const float*)d_in[0];
    const void*  L    = d_in[1];
    const float* W_ih = (const float*)d_in[2];
    const float* W_hh = (const float*)d_in[3];
    const float* b_ih = (const float*)d_in[4];
    const float* b_hh = (const float*)d_in[5];
    float* out = (float*)d_out;

    k_fused<<<Bn, 128>>>(x, L, W_ih, W_hh, b_ih, b_hh, out);
}